// round 3
// baseline (speedup 1.0000x reference)
#include <cuda_runtime.h>
#include <stdint.h>

#define Mv 128          // variants
#define Nv 256          // positions
#define Cv 22           // classes
#define TILE (Cv*Cv)    // 484 floats per (i,j) tile
#define JC 8            // j per chunk
#define NCHUNK (Nv/JC)  // 32
#define NSTAGES 3
#define STAGE_FLOATS (JC*TILE)        // 3872 floats
#define STAGE_BYTES  (STAGE_FLOATS*4) // 15488 B (16B multiple)
#define CHALF 11

// pooled-delta partials g_part[i][m], and grid-barrier state
__device__ float g_part[Nv*Mv];
__device__ unsigned g_cnt = 0;
__device__ volatile unsigned g_flag = 0;

__device__ __forceinline__ unsigned smem_u32(const void* p) {
    return (unsigned)__cvta_generic_to_shared(p);
}

__global__ __launch_bounds__(256, 2) void fused_kernel(
    const int*   __restrict__ variant,   // [Mv, Nv]
    const float* __restrict__ vmask,     // [Mv, Nv]
    const float* __restrict__ eij,       // [Nv, Nv, Cv, Cv]
    const float* __restrict__ ei,        // [Nv, Cv]
    const float* __restrict__ mask_vec,  // [Cv]
    const float* __restrict__ sigma,     // [1]
    float* __restrict__ motifs,          // [Mv, Nv, Cv]
    float* __restrict__ logits,          // [Mv, Nv]
    float* __restrict__ vlog)            // [Mv]
{
    __shared__ __align__(128) float sE[NSTAGES][STAGE_FLOATS];   // 46464 B
    __shared__ __align__(8) unsigned long long mbar[NSTAGES];
    __shared__ float smask[32];
    __shared__ float sei[Cv];
    __shared__ float slog[Mv];
    __shared__ float red[256];

    const int i  = blockIdx.x;           // position
    const int t  = threadIdx.x;
    const int m  = t & (Mv - 1);
    const int c0 = (t >> 7) * CHALF;

    if (t < Cv) { smask[t] = mask_vec[t]; sei[t] = ei[i * Cv + t]; }
    if (t == 0) {
        #pragma unroll
        for (int s = 0; s < NSTAGES; ++s) {
            unsigned a = smem_u32(&mbar[s]);
            asm volatile("mbarrier.init.shared.b64 [%0], 1;" :: "r"(a));
        }
    }
    __syncthreads();

    const char* gsrc = (const char*)(eij + (size_t)i * (Nv * TILE));
    const int4* vrow = (const int4*)(variant + m * Nv);

    // prime 2 chunks via TMA bulk copy (thread 0 only)
    if (t == 0) {
        #pragma unroll
        for (int k = 0; k < 2; ++k) {
            unsigned bar = smem_u32(&mbar[k]);
            asm volatile("mbarrier.arrive.expect_tx.shared::cta.b64 _, [%0], %1;"
                         :: "r"(bar), "r"((unsigned)STAGE_BYTES));
            unsigned dst = smem_u32(&sE[k][0]);
            asm volatile("cp.async.bulk.shared::cta.global.mbarrier::complete_tx::bytes "
                         "[%0], [%1], %2, [%3];"
                         :: "r"(dst), "l"(gsrc + (size_t)k * STAGE_BYTES),
                            "r"((unsigned)STAGE_BYTES), "r"(bar) : "memory");
        }
    }

    float acc[CHALF];
    #pragma unroll
    for (int cc = 0; cc < CHALF; ++cc) acc[cc] = 0.0f;

    for (int k = 0; k < NCHUNK; ++k) {
        const int s = k % NSTAGES;
        const unsigned ph = (unsigned)(k / NSTAGES) & 1u;

        // class ids for this chunk (independent of TMA data — load before wait)
        int4 va = vrow[k * 2];
        int4 vb = vrow[k * 2 + 1];

        // wait for chunk k
        {
            unsigned bar = smem_u32(&mbar[s]);
            unsigned done;
            asm volatile("{\n .reg .pred p;\n"
                         " mbarrier.try_wait.parity.acquire.cta.shared::cta.b64 p, [%1], %2;\n"
                         " selp.b32 %0, 1, 0, p;\n}"
                         : "=r"(done) : "r"(bar), "r"(ph) : "memory");
            while (!done) {
                asm volatile("{\n .reg .pred p;\n"
                             " mbarrier.try_wait.parity.acquire.cta.shared::cta.b64 p, [%1], %2, 0x989680;\n"
                             " selp.b32 %0, 1, 0, p;\n}"
                             : "=r"(done) : "r"(bar), "r"(ph) : "memory");
            }
        }

        int d8[8] = {va.x, va.y, va.z, va.w, vb.x, vb.y, vb.z, vb.w};
        float s8[8];
        #pragma unroll
        for (int jj = 0; jj < 8; ++jj) s8[jj] = smask[d8[jj]];

        const float* buf = sE[s];
        #pragma unroll
        for (int jj = 0; jj < JC; ++jj) {
            const float* row = buf + jj * TILE + c0 * Cv + d8[jj];
            const float sc = s8[jj];
            #pragma unroll
            for (int cc = 0; cc < CHALF; ++cc)
                acc[cc] = fmaf(sc, row[cc * Cv], acc[cc]);   // conflict-free LDS
        }

        __syncthreads();   // all threads done with chunk k-1's stage before overwrite
        if (t == 0 && k + 2 < NCHUNK) {
            const int kn = k + 2;
            unsigned bar = smem_u32(&mbar[kn % NSTAGES]);
            asm volatile("mbarrier.arrive.expect_tx.shared::cta.b64 _, [%0], %1;"
                         :: "r"(bar), "r"((unsigned)STAGE_BYTES));
            unsigned dst = smem_u32(&sE[kn % NSTAGES][0]);
            asm volatile("cp.async.bulk.shared::cta.global.mbarrier::complete_tx::bytes "
                         "[%0], [%1], %2, [%3];"
                         :: "r"(dst), "l"(gsrc + (size_t)kn * STAGE_BYTES),
                            "r"((unsigned)STAGE_BYTES), "r"(bar) : "memory");
        }
    }

    // ---- epilogue: motifs, logits, pooled-delta partials ----
    const int vmi = variant[m * Nv + i];
    float* mout = motifs + ((size_t)m * Nv + i) * Cv;
    float myl = 0.0f;
    const bool own = (vmi >= c0) && (vmi < c0 + CHALF);
    #pragma unroll
    for (int cc = 0; cc < CHALF; ++cc) {
        const int c = c0 + cc;
        const float v = acc[cc] + sei[c];
        mout[c] = v;
        if (c == vmi) myl = v;
    }
    if (own) slog[m] = myl;
    __syncthreads();

    if (t < Mv) {
        const float lm = slog[t];
        logits[t * Nv + i] = lm;
        const float w = vmask[t * Nv + i] * vmask[i];
        g_part[i * Mv + t] = (lm - slog[0]) * w * sigma[0];
    }

    // ---- software grid barrier (all 256 CTAs co-resident by construction) ----
    __threadfence();
    __syncthreads();
    if (t == 0) {
        unsigned cur = g_flag;
        unsigned old = atomicInc(&g_cnt, Nv - 1);   // self-wraps to 0
        if (old == Nv - 1) g_flag = cur + 1;        // release
        else while (g_flag == cur) { }              // spin
    }
    __syncthreads();
    __threadfence();

    // ---- fused reduce: CTA i<128 computes vlog[i] = sum_j g_part[j][i] ----
    if (i < Mv) {
        red[t] = g_part[t * Mv + i];
        __syncthreads();
        #pragma unroll
        for (int st = 128; st > 0; st >>= 1) {
            if (t < st) red[t] += red[t + st];
            __syncthreads();
        }
        if (t == 0) vlog[i] = red[0];
    }
}

// ---------------------------------------------------------------------------
extern "C" void kernel_launch(void* const* d_in, const int* in_sizes, int n_in,
                              void* d_out, int out_size) {
    int idx_eij = 2, idx_ei = 3, idx_mask = 4, idx_sigma = 5;
    int big1 = 0, big2 = 1;
    {
        int b1 = -1, b2 = -1;
        for (int q = 0; q < n_in; ++q) {
            int s = in_sizes[q];
            if (s == Nv * Nv * Cv * Cv)      idx_eij = q;
            else if (s == Nv * Cv)           idx_ei = q;
            else if (s == Cv)                idx_mask = q;
            else if (s == 1)                 idx_sigma = q;
            else if (s == Mv * Nv) { if (b1 < 0) b1 = q; else b2 = q; }
        }
        if (b1 >= 0) big1 = b1;
        if (b2 >= 0) big2 = b2;
    }

    const int*   variant = (const int*)d_in[big1];
    const float* vmask   = (const float*)d_in[big2];
    const float* eij     = (const float*)d_in[idx_eij];
    const float* ei      = (const float*)d_in[idx_ei];
    const float* maskv   = (const float*)d_in[idx_mask];
    const float* sigma   = (const float*)d_in[idx_sigma];

    float* out    = (float*)d_out;
    float* motifs = out;                               // [128,256,22]
    float* logits = out + (size_t)Mv * Nv * Cv;        // [128,256]
    float* vlog   = logits + (size_t)Mv * Nv;          // [128,1]

    fused_kernel<<<Nv, 256>>>(variant, vmask, eij, ei, maskv, sigma,
                              motifs, logits, vlog);
}

// round 7
// speedup vs baseline: 1.3596x; 1.3596x over previous
#include <cuda_runtime.h>
#include <stdint.h>

#define Mv 128          // variants
#define Nv 256          // positions
#define Cv 22           // classes
#define TILE (Cv*Cv)    // 484 floats per (i,j) tile
#define JC 8            // j per chunk
#define NCHUNK (Nv/JC)  // 32
#define NSTAGES 3
#define STAGE_FLOATS (JC*TILE)        // 3872 floats
#define STAGE_BYTES  (STAGE_FLOATS*4) // 15488 B
#define CHALF 11
#define NB 256

__device__ unsigned g_dselp[(Nv/4) * Mv];   // [j4][m], 4 packed classes/word
__device__ float    g_part[Nv * Mv];        // [i][m]
__device__ unsigned g_cnt = 0;
__device__ volatile unsigned g_flag = 0;

__device__ __forceinline__ unsigned smem_u32(const void* p) {
    return (unsigned)__cvta_generic_to_shared(p);
}

// ---------------------------------------------------------------------------
// prep: variant [m][j] ints -> packed bytes [j4][m] (coalesced consumer reads)
// ---------------------------------------------------------------------------
__global__ void prep_kernel(const int* __restrict__ variant) {
    int tid = blockIdx.x * blockDim.x + threadIdx.x;    // 8192 = 128m x 64 j4
    int m  = tid >> 6;
    int j4 = tid & 63;
    int4 v = ((const int4*)variant)[m * 64 + j4];       // coalesced
    unsigned w = (unsigned)v.x | ((unsigned)v.y << 8) |
                 ((unsigned)v.z << 16) | ((unsigned)v.w << 24);
    g_dselp[j4 * Mv + m] = w;
}

// ---------------------------------------------------------------------------
__global__ __launch_bounds__(256, 2) void fused_kernel(
    const int*   __restrict__ variant,
    const float* __restrict__ vmask,
    const float* __restrict__ eij,
    const float* __restrict__ ei,
    const float* __restrict__ mask_vec,
    const float* __restrict__ sigma,
    float* __restrict__ motifs,      // [Mv,Nv,Cv]
    float* __restrict__ logits,      // [Mv,Nv]
    float* __restrict__ vlog)        // [Mv]
{
    __shared__ __align__(128) float sE[NSTAGES][STAGE_FLOATS];   // 46464 B static
    __shared__ __align__(8) unsigned long long mbar[NSTAGES];
    __shared__ float smask[32];
    __shared__ float sei[Cv];
    __shared__ float slog[Mv];
    __shared__ float red[256];

    const int i  = blockIdx.x;
    const int t  = threadIdx.x;
    const int m  = t & (Mv - 1);
    const int c0 = (t >> 7) * CHALF;

    if (t < Cv) { smask[t] = mask_vec[t]; sei[t] = ei[i * Cv + t]; }
    if (t == 0) {
        #pragma unroll
        for (int s = 0; s < NSTAGES; ++s)
            asm volatile("mbarrier.init.shared.b64 [%0], 1;"
                         :: "r"(smem_u32(&mbar[s])));
    }
    __syncthreads();

    const char* gsrc = (const char*)(eij + (size_t)i * (Nv * TILE));

    // prime 2 chunks (r3-proven protocol)
    if (t == 0) {
        #pragma unroll
        for (int k = 0; k < 2; ++k) {
            unsigned bar = smem_u32(&mbar[k]);
            asm volatile("mbarrier.arrive.expect_tx.shared::cta.b64 _, [%0], %1;"
                         :: "r"(bar), "r"((unsigned)STAGE_BYTES));
            asm volatile("cp.async.bulk.shared::cta.global.mbarrier::complete_tx::bytes "
                         "[%0], [%1], %2, [%3];"
                         :: "r"(smem_u32(&sE[k][0])),
                            "l"(gsrc + (size_t)k * STAGE_BYTES),
                            "r"((unsigned)STAGE_BYTES), "r"(bar) : "memory");
        }
    }

    float acc[CHALF];
    #pragma unroll
    for (int cc = 0; cc < CHALF; ++cc) acc[cc] = 0.0f;

    for (int k = 0; k < NCHUNK; ++k) {
        const int s = k % NSTAGES;
        const unsigned ph = (unsigned)(k / NSTAGES) & 1u;

        // 2 coalesced words = 8 class ids (independent of TMA data)
        unsigned w0 = g_dselp[(k * 2 + 0) * Mv + m];
        unsigned w1 = g_dselp[(k * 2 + 1) * Mv + m];

        {   // wait for chunk k (r3-proven)
            unsigned bar = smem_u32(&mbar[s]);
            unsigned done;
            asm volatile("{\n .reg .pred p;\n"
                         " mbarrier.try_wait.parity.acquire.cta.shared::cta.b64 p, [%1], %2;\n"
                         " selp.b32 %0, 1, 0, p;\n}"
                         : "=r"(done) : "r"(bar), "r"(ph) : "memory");
            while (!done) {
                asm volatile("{\n .reg .pred p;\n"
                             " mbarrier.try_wait.parity.acquire.cta.shared::cta.b64 p, [%1], %2, 0x989680;\n"
                             " selp.b32 %0, 1, 0, p;\n}"
                             : "=r"(done) : "r"(bar), "r"(ph) : "memory");
            }
        }

        int d8[8];
        #pragma unroll
        for (int b = 0; b < 4; ++b) {
            d8[b]     = (w0 >> (8 * b)) & 0xFF;
            d8[4 + b] = (w1 >> (8 * b)) & 0xFF;
        }
        float s8[8];
        #pragma unroll
        for (int jj = 0; jj < 8; ++jj) s8[jj] = smask[d8[jj]];

        const float* buf = sE[s];
        #pragma unroll
        for (int jj = 0; jj < JC; ++jj) {
            const float* row = buf + jj * TILE + c0 * Cv + d8[jj];
            const float sc = s8[jj];
            #pragma unroll
            for (int cc = 0; cc < CHALF; ++cc)
                acc[cc] = fmaf(sc, row[cc * Cv], acc[cc]);   // conflict-free LDS
        }

        __syncthreads();   // all threads done with chunk k -> stage (k-1)%3 reusable
        if (t == 0 && k + 2 < NCHUNK) {
            const int kn = k + 2;
            unsigned bar = smem_u32(&mbar[kn % NSTAGES]);
            asm volatile("mbarrier.arrive.expect_tx.shared::cta.b64 _, [%0], %1;"
                         :: "r"(bar), "r"((unsigned)STAGE_BYTES));
            asm volatile("cp.async.bulk.shared::cta.global.mbarrier::complete_tx::bytes "
                         "[%0], [%1], %2, [%3];"
                         :: "r"(smem_u32(&sE[kn % NSTAGES][0])),
                            "l"(gsrc + (size_t)kn * STAGE_BYTES),
                            "r"((unsigned)STAGE_BYTES), "r"(bar) : "memory");
        }
    }

    // ---- epilogue: motifs, logits, pooled-delta partials (r3-proven) ----
    const int vmi = variant[m * Nv + i];
    float* mout = motifs + ((size_t)m * Nv + i) * Cv;
    float myl = 0.0f;
    const bool own = (vmi >= c0) && (vmi < c0 + CHALF);
    #pragma unroll
    for (int cc = 0; cc < CHALF; ++cc) {
        const int c = c0 + cc;
        const float v = acc[cc] + sei[c];
        mout[c] = v;
        if (c == vmi) myl = v;
    }
    if (own) slog[m] = myl;
    __syncthreads();

    if (t < Mv) {
        const float lm = slog[t];
        logits[t * Nv + i] = lm;
        const float w = vmask[t * Nv + i] * vmask[i];
        g_part[i * Mv + t] = (lm - slog[0]) * w * sigma[0];
    }

    // ---- software grid barrier (256 CTAs @ 2/SM, r3-proven) ----
    __threadfence();
    __syncthreads();
    if (t == 0) {
        unsigned cur = g_flag;
        unsigned old = atomicInc(&g_cnt, NB - 1);    // wraps to 0
        if (old == NB - 1) g_flag = cur + 1;
        else while (g_flag == cur) { }
    }
    __syncthreads();
    __threadfence();

    // ---- fused reduce: CTA i<128 computes vlog[i] = sum_j g_part[j][i] ----
    if (i < Mv) {
        red[t] = g_part[t * Mv + i];
        __syncthreads();
        #pragma unroll
        for (int st = 128; st > 0; st >>= 1) {
            if (t < st) red[t] += red[t + st];
            __syncthreads();
        }
        if (t == 0) vlog[i] = red[0];
    }
}

// ---------------------------------------------------------------------------
extern "C" void kernel_launch(void* const* d_in, const int* in_sizes, int n_in,
                              void* d_out, int out_size) {
    int idx_eij = 2, idx_ei = 3, idx_mask = 4, idx_sigma = 5;
    int big1 = 0, big2 = 1;
    {
        int b1 = -1, b2 = -1;
        for (int q = 0; q < n_in; ++q) {
            int s = in_sizes[q];
            if (s == Nv * Nv * Cv * Cv)      idx_eij = q;
            else if (s == Nv * Cv)           idx_ei = q;
            else if (s == Cv)                idx_mask = q;
            else if (s == 1)                 idx_sigma = q;
            else if (s == Mv * Nv) { if (b1 < 0) b1 = q; else b2 = q; }
        }
        if (b1 >= 0) big1 = b1;
        if (b2 >= 0) big2 = b2;
    }

    const int*   variant = (const int*)d_in[big1];
    const float* vmask   = (const float*)d_in[big2];
    const float* eij     = (const float*)d_in[idx_eij];
    const float* ei      = (const float*)d_in[idx_ei];
    const float* maskv   = (const float*)d_in[idx_mask];
    const float* sigma   = (const float*)d_in[idx_sigma];

    float* out    = (float*)d_out;
    float* motifs = out;                               // [128,256,22]
    float* logits = out + (size_t)Mv * Nv * Cv;        // [128,256]
    float* vlog   = logits + (size_t)Mv * Nv;          // [128,1]

    prep_kernel<<<32, 256>>>(variant);
    fused_kernel<<<NB, 256>>>(variant, vmask, eij, ei, maskv, sigma,
                              motifs, logits, vlog);
}